// round 4
// baseline (speedup 1.0000x reference)
#include <cuda_runtime.h>
#include <math.h>
#include <cfloat>
#include <stdint.h>

// ---------------- problem constants ----------------
#define BB     2
#define NQ     2048
#define NK     2048
#define DIMM   512
#define HH     8
#define DH     64
#define INNER  512
#define NBANDS 32
#define DWP    577      // DIM + 2*NUM_BANDS + 1
#define TOPKK  64
#define MROWS  (BB*NQ)  // 4096

// ---------------- scratch (device globals; no cudaMalloc allowed) ----------------
__device__ float g_enc[NQ * 65];
__device__ float g_Aq[(size_t)MROWS * DWP];
__device__ float g_Ak[(size_t)MROWS * DWP];
__device__ float g_Q [(size_t)MROWS * INNER];
__device__ float g_K [(size_t)MROWS * INNER];
__device__ float g_V [(size_t)MROWS * INNER];
__device__ float g_O [(size_t)MROWS * INNER];

// ---------------- fourier encode ----------------
__global__ void enc_kernel() {
    int i = blockIdx.x * blockDim.x + threadIdx.x;
    if (i >= NQ) return;
    float step = 2.0f / 2047.0f;
    float pos = fmaf((float)i, step, -1.0f);
    g_enc[i * 65 + 64] = pos;
    #pragma unroll 4
    for (int b = 0; b < NBANDS; b++) {
        float sc = 1.0f + 29.0f * (float)b / 31.0f;   // linspace(1, 30, 32)
        float xs = (pos * sc) * 3.14159265358979323846f;
        g_enc[i * 65 + b]          = sinf(xs);
        g_enc[i * 65 + NBANDS + b] = cosf(xs);
    }
}

// ---------------- concat [x | enc] and [context | enc] ----------------
__global__ void concat_kernel(const float* __restrict__ x, const float* __restrict__ ctx) {
    int idx = blockIdx.x * blockDim.x + threadIdx.x;
    const int total = MROWS * DWP;
    if (idx >= total) return;
    int row = idx / DWP;
    int c   = idx - row * DWP;
    if (c < DIMM) {
        g_Aq[idx] = x  [(size_t)row * DIMM + c];
        g_Ak[idx] = ctx[(size_t)row * DIMM + c];
    } else {
        int i = row & (NQ - 1);
        float e = g_enc[i * 65 + (c - DIMM)];
        g_Aq[idx] = e;
        g_Ak[idx] = e;
    }
}

// ---------------- fp32 tiled GEMM: C[M,N] = A[M,K] @ W[K,N] + bias ----------------
// (unchanged from round 3: bit-exact projections)
__global__ __launch_bounds__(256) void gemm_bias(
    const float* __restrict__ A, int lda,
    const float* __restrict__ W,
    const float* __restrict__ bias,
    float* __restrict__ C,
    int M, int N, int K)
{
    __shared__ float As[16][132];
    __shared__ float Bs[16][64];

    int bm = blockIdx.y * 128;
    int bn = blockIdx.x * 64;
    int tid = threadIdx.x;
    int tx = tid & 15;
    int ty = tid >> 4;

    float acc[8][4];
    #pragma unroll
    for (int i = 0; i < 8; i++)
        #pragma unroll
        for (int j = 0; j < 4; j++) acc[i][j] = 0.0f;

    for (int k0 = 0; k0 < K; k0 += 16) {
        #pragma unroll
        for (int i = 0; i < 8; i++) {
            int e = tid + i * 256;
            int m = e >> 4, kk = e & 15;
            int gk = k0 + kk;
            As[kk][m] = (gk < K) ? A[(size_t)(bm + m) * lda + gk] : 0.0f;
        }
        {
            int kk = tid >> 4;
            int nc = (tid & 15) << 2;
            int gk = k0 + kk;
            float4 v = make_float4(0.f, 0.f, 0.f, 0.f);
            if (gk < K) v = *(const float4*)(W + (size_t)gk * N + bn + nc);
            *(float4*)&Bs[kk][nc] = v;
        }
        __syncthreads();
        #pragma unroll
        for (int kk = 0; kk < 16; kk++) {
            float4 a0 = *(const float4*)&As[kk][ty * 8];
            float4 a1 = *(const float4*)&As[kk][ty * 8 + 4];
            float4 bv = *(const float4*)&Bs[kk][tx * 4];
            float av[8] = {a0.x, a0.y, a0.z, a0.w, a1.x, a1.y, a1.z, a1.w};
            float bw[4] = {bv.x, bv.y, bv.z, bv.w};
            #pragma unroll
            for (int i = 0; i < 8; i++)
                #pragma unroll
                for (int j = 0; j < 4; j++)
                    acc[i][j] = fmaf(av[i], bw[j], acc[i][j]);
        }
        __syncthreads();
    }

    float4 bb = *(const float4*)(bias + bn + tx * 4);
    #pragma unroll
    for (int i = 0; i < 8; i++) {
        float4 o;
        o.x = acc[i][0] + bb.x;
        o.y = acc[i][1] + bb.y;
        o.z = acc[i][2] + bb.z;
        o.w = acc[i][3] + bb.w;
        *(float4*)(C + (size_t)(bm + ty * 8 + i) * N + bn + tx * 4) = o;
    }
}

// ---------------- fused attention v2 ----------------
// QT=8 query rows per CTA, 256 threads, 2q x 4k register tiles,
// K tile staged dim-major (Ks4[d4][row], +1 pad) via double-buffered cp.async.
// Per-accumulator FMA order identical to v1 -> bit-identical scores/selection.
#define QT2  8
#define CKC2 256
#define NCH  (NK / CKC2)   // 8
#define CAP  128

struct AttnSmem2 {
    float  s[QT2][NK];              // 65536 B
    float4 Ks4[2][16][CKC2 + 1];    // 131584 B (pad -> conflict-free STS & LDS)
    float4 qs4[QT2][16];            // 2048 B
    int    hist[QT2][256];          // 8192 B
    float  plist[QT2][CAP];         // 4096 B
    unsigned short list[QT2][CAP];  // 2048 B
    int    cnt[QT2];                // 32 B
};                                   // ~213.5 KB total

__device__ __forceinline__ unsigned key_of(float f) {
    unsigned u = __float_as_uint(f);
    return (u & 0x80000000u) ? ~u : (u | 0x80000000u);
}
__device__ __forceinline__ float inv_key(unsigned k) {
    unsigned u = (k & 0x80000000u) ? (k ^ 0x80000000u) : ~k;
    return __uint_as_float(u);
}

__device__ __forceinline__ void cp_async16(void* smem_dst, const void* gmem_src) {
    uint32_t sa = (uint32_t)__cvta_generic_to_shared(smem_dst);
    asm volatile("cp.async.cg.shared.global [%0], [%1], 16;" :: "r"(sa), "l"(gmem_src));
}
__device__ __forceinline__ void cp_commit() {
    asm volatile("cp.async.commit_group;");
}
template <int N>
__device__ __forceinline__ void cp_wait() {
    asm volatile("cp.async.wait_group %0;" :: "n"(N) : "memory");
}

__device__ __forceinline__ void load_chunk(AttnSmem2* sm, const float* __restrict__ Kg,
                                           int base_k, int kc, int buf, int tid, int hoff) {
    const float* src = Kg + (size_t)(base_k + kc) * INNER + hoff;
    #pragma unroll
    for (int i = 0; i < 16; i++) {
        int e = tid + i * 256;
        int row = e >> 4, d4 = e & 15;
        cp_async16(&sm->Ks4[buf][d4][row], src + (size_t)row * INNER + d4 * 4);
    }
}

__global__ __launch_bounds__(256) void attn_kernel(
    const float* __restrict__ Qg, const float* __restrict__ Kg,
    const float* __restrict__ Vg,
    float* __restrict__ Og)
{
    extern __shared__ char smraw[];
    AttnSmem2* sm = reinterpret_cast<AttnSmem2*>(smraw);

    int tile = blockIdx.x;            // b*2048 + h*256 + qt
    int qt = tile & 255;
    int h  = (tile >> 8) & 7;
    int b  = tile >> 11;
    int tid = threadIdx.x;

    int base_q = b * NQ + qt * QT2;
    int base_k = b * NK;
    int hoff = h * DH;

    // stage q (8 rows x 16 float4)
    if (tid < QT2 * 16) {
        int r = tid >> 4, d4 = tid & 15;
        sm->qs4[r][d4] = *(const float4*)(Qg + (size_t)(base_q + r) * INNER + hoff + d4 * 4);
    }

    // preload K chunk 0
    load_chunk(sm, Kg, base_k, 0, 0, tid, hoff);
    cp_commit();

    int qg = tid >> 6;        // 0..3 -> q rows {2qg, 2qg+1}
    int kg = tid & 63;        // k columns {kg, kg+64, kg+128, kg+192} in chunk
    int q0r = 2 * qg, q1r = q0r + 1;

    for (int c = 0; c < NCH; c++) {
        if (c + 1 < NCH) {
            load_chunk(sm, Kg, base_k, (c + 1) * CKC2, (c + 1) & 1, tid, hoff);
            cp_commit();
            cp_wait<1>();
        } else {
            cp_wait<0>();
        }
        __syncthreads();

        int buf = c & 1;
        float a0[4] = {0.f, 0.f, 0.f, 0.f};
        float a1[4] = {0.f, 0.f, 0.f, 0.f};
        #pragma unroll
        for (int d4 = 0; d4 < 16; d4++) {
            float4 q0 = sm->qs4[q0r][d4];
            float4 q1 = sm->qs4[q1r][d4];
            #pragma unroll
            for (int j = 0; j < 4; j++) {
                float4 kv = sm->Ks4[buf][d4][kg + 64 * j];
                a0[j] = fmaf(q0.x, kv.x, a0[j]);
                a0[j] = fmaf(q0.y, kv.y, a0[j]);
                a0[j] = fmaf(q0.z, kv.z, a0[j]);
                a0[j] = fmaf(q0.w, kv.w, a0[j]);
                a1[j] = fmaf(q1.x, kv.x, a1[j]);
                a1[j] = fmaf(q1.y, kv.y, a1[j]);
                a1[j] = fmaf(q1.z, kv.z, a1[j]);
                a1[j] = fmaf(q1.w, kv.w, a1[j]);
            }
        }
        int kc = c * CKC2;
        #pragma unroll
        for (int j = 0; j < 4; j++) {
            sm->s[q0r][kc + kg + 64 * j] = a0[j] * 0.125f;
            sm->s[q1r][kc + kg + 64 * j] = a1[j] * 0.125f;
        }
        __syncthreads();
    }

    // ---- per-warp exact radix select of the 64th-largest value ----
    const unsigned full = 0xFFFFFFFFu;
    int warp = tid >> 5, lane = tid & 31;
    int r = warp;                       // 8 warps == QT2 rows

    unsigned prefix = 0, pmask = 0;
    int krem = TOPKK;
    #pragma unroll
    for (int shift = 24; shift >= 0; shift -= 8) {
        for (int bi = lane; bi < 256; bi += 32) sm->hist[r][bi] = 0;
        __syncwarp();
        for (int j = lane; j < NK; j += 32) {
            unsigned u = key_of(sm->s[r][j]);
            if ((u & pmask) == prefix)
                atomicAdd(&sm->hist[r][(u >> shift) & 255], 1);
        }
        __syncwarp();
        int basebin = 255 - 8 * lane;
        int gsum = 0;
        #pragma unroll
        for (int i = 0; i < 8; i++) gsum += sm->hist[r][basebin - i];
        int inc = gsum;
        #pragma unroll
        for (int off = 1; off < 32; off <<= 1) {
            int v = __shfl_up_sync(full, inc, off);
            if (lane >= off) inc += v;
        }
        int excl = inc - gsum;
        unsigned bal = __ballot_sync(full, (excl < krem) && (krem <= inc));
        int selLane = __ffs(bal) - 1;
        int exclSel = __shfl_sync(full, excl, selLane);
        int need = krem - exclSel;
        int gb = 255 - 8 * selLane;
        int selBin = -1, cc = 0, newNeed = 0;
        for (int i = 0; i < 8; i++) {
            int hh = sm->hist[r][gb - i];
            if (selBin < 0 && need <= cc + hh) { selBin = gb - i; newNeed = need - cc; }
            cc += hh;
        }
        krem = newNeed;
        prefix |= ((unsigned)selBin) << shift;
        pmask  |= (0xFFu << shift);
        __syncwarp();
    }
    float vkf = inv_key(prefix);

    // ---- deterministic gather of kept indices + row max ----
    int cbase = 0;
    float m = -FLT_MAX;
    for (int j0 = 0; j0 < NK; j0 += 32) {
        int j = j0 + lane;
        float sv = sm->s[r][j];
        bool keep = (sv >= vkf);
        unsigned bal = __ballot_sync(full, keep);
        if (keep) {
            int pos = cbase + __popc(bal & ((1u << lane) - 1u));
            if (pos < CAP) sm->list[r][pos] = (unsigned short)j;
            m = fmaxf(m, sv);
        }
        cbase += __popc(bal);
    }
    #pragma unroll
    for (int off = 16; off; off >>= 1) m = fmaxf(m, __shfl_xor_sync(full, m, off));
    if (lane == 0) sm->cnt[r] = cbase;
    __syncwarp();
    int n = sm->cnt[r];

    float acc0 = 0.f, acc1 = 0.f, sum = 0.f;
    const float* Vb = Vg + (size_t)base_k * INNER + hoff;

    if (n <= CAP) {
        float ls = 0.f;
        for (int e = lane; e < n; e += 32) {
            int j = sm->list[r][e];
            float p = expf(sm->s[r][j] - m);
            sm->plist[r][e] = p;
            ls += p;
        }
        #pragma unroll
        for (int off = 16; off; off >>= 1) ls += __shfl_xor_sync(full, ls, off);
        sum = ls;
        __syncwarp();
        #pragma unroll 4
        for (int e = 0; e < n; e++) {
            float p = sm->plist[r][e];
            int j = sm->list[r][e];
            const float* vp = Vb + (size_t)j * INNER;
            acc0 = fmaf(p, vp[lane],      acc0);
            acc1 = fmaf(p, vp[lane + 32], acc1);
        }
    } else {
        float ls = 0.f;
        for (int j = 0; j < NK; j++) {
            float sv = sm->s[r][j];
            if (sv >= vkf) {
                float p = expf(sv - m);
                ls += p;
                const float* vp = Vb + (size_t)j * INNER;
                acc0 = fmaf(p, vp[lane],      acc0);
                acc1 = fmaf(p, vp[lane + 32], acc1);
            }
        }
        sum = ls;
    }

    float invs = 1.0f / sum;
    float* op = Og + (size_t)(base_q + r) * INNER + hoff;
    op[lane]      = acc0 * invs;
    op[lane + 32] = acc1 * invs;
}

// ---------------- launch ----------------
extern "C" void kernel_launch(void* const* d_in, const int* in_sizes, int n_in,
                              void* d_out, int out_size)
{
    const float* x       = (const float*)d_in[0];
    const float* context = (const float*)d_in[1];
    // d_in[2]/d_in[3] are the bool masks; constant all-True in this problem.
    const float* Wq = (const float*)d_in[4];
    const float* bq = (const float*)d_in[5];
    const float* Wk = (const float*)d_in[6];
    const float* bk = (const float*)d_in[7];
    const float* Wv = (const float*)d_in[8];
    const float* bv = (const float*)d_in[9];
    const float* Wo = (const float*)d_in[10];
    const float* bo = (const float*)d_in[11];
    float* out = (float*)d_out;

    void *pAq, *pAk, *pQ, *pK, *pV, *pO;
    cudaGetSymbolAddress(&pAq, g_Aq);
    cudaGetSymbolAddress(&pAk, g_Ak);
    cudaGetSymbolAddress(&pQ,  g_Q);
    cudaGetSymbolAddress(&pK,  g_K);
    cudaGetSymbolAddress(&pV,  g_V);
    cudaGetSymbolAddress(&pO,  g_O);
    float* Aq = (float*)pAq; float* Ak = (float*)pAk;
    float* Qd = (float*)pQ;  float* Kd = (float*)pK;
    float* Vd = (float*)pV;  float* Od = (float*)pO;

    cudaFuncSetAttribute(attn_kernel, cudaFuncAttributeMaxDynamicSharedMemorySize,
                         (int)sizeof(AttnSmem2));

    enc_kernel<<<(NQ + 255) / 256, 256>>>();

    int tot = MROWS * DWP;
    concat_kernel<<<(tot + 255) / 256, 256>>>(x, context);

    dim3 gg(INNER / 64, MROWS / 128);   // (8, 32)
    gemm_bias<<<gg, 256>>>(Aq, DWP, Wq, bq, Qd, MROWS, INNER, DWP);
    gemm_bias<<<gg, 256>>>(Ak, DWP, Wk, bk, Kd, MROWS, INNER, DWP);
    gemm_bias<<<gg, 256>>>(context, DIMM, Wv, bv, Vd, MROWS, INNER, DIMM);

    attn_kernel<<<BB * HH * (NQ / QT2), 256, sizeof(AttnSmem2)>>>(Qd, Kd, Vd, Od);

    gemm_bias<<<gg, 256>>>(Od, INNER, Wo, bo, out, MROWS, DIMM, INNER);
}

// round 5
// speedup vs baseline: 1.0846x; 1.0846x over previous
#include <cuda_runtime.h>
#include <math.h>
#include <cfloat>
#include <stdint.h>

// ---------------- problem constants ----------------
#define BB     2
#define NQ     2048
#define NK     2048
#define DIMM   512
#define HH     8
#define DH     64
#define INNER  512
#define NBANDS 32
#define DWP    577      // DIM + 2*NUM_BANDS + 1
#define TOPKK  64
#define MROWS  (BB*NQ)  // 4096

// ---------------- scratch (device globals; no cudaMalloc allowed) ----------------
__device__ float g_enc[NQ * 65];
__device__ float g_Aq[(size_t)MROWS * DWP];
__device__ float g_Ak[(size_t)MROWS * DWP];
__device__ float g_Q [(size_t)MROWS * INNER];
__device__ float g_K [(size_t)MROWS * INNER];
__device__ float g_V [(size_t)MROWS * INNER];
__device__ float g_O [(size_t)MROWS * INNER];

// ---------------- fourier encode ----------------
__global__ void enc_kernel() {
    int i = blockIdx.x * blockDim.x + threadIdx.x;
    if (i >= NQ) return;
    float step = 2.0f / 2047.0f;
    float pos = fmaf((float)i, step, -1.0f);
    g_enc[i * 65 + 64] = pos;
    #pragma unroll 4
    for (int b = 0; b < NBANDS; b++) {
        float sc = 1.0f + 29.0f * (float)b / 31.0f;   // linspace(1, 30, 32)
        float xs = (pos * sc) * 3.14159265358979323846f;
        g_enc[i * 65 + b]          = sinf(xs);
        g_enc[i * 65 + NBANDS + b] = cosf(xs);
    }
}

// ---------------- concat [x | enc] and [context | enc] ----------------
__global__ void concat_kernel(const float* __restrict__ x, const float* __restrict__ ctx) {
    int idx = blockIdx.x * blockDim.x + threadIdx.x;
    const int total = MROWS * DWP;
    if (idx >= total) return;
    int row = idx / DWP;
    int c   = idx - row * DWP;
    if (c < DIMM) {
        g_Aq[idx] = x  [(size_t)row * DIMM + c];
        g_Ak[idx] = ctx[(size_t)row * DIMM + c];
    } else {
        int i = row & (NQ - 1);
        float e = g_enc[i * 65 + (c - DIMM)];
        g_Aq[idx] = e;
        g_Ak[idx] = e;
    }
}

// ---------------- fp32 tiled GEMM (unchanged: bit-exact projections) ----------------
__global__ __launch_bounds__(256) void gemm_bias(
    const float* __restrict__ A, int lda,
    const float* __restrict__ W,
    const float* __restrict__ bias,
    float* __restrict__ C,
    int M, int N, int K)
{
    __shared__ float As[16][132];
    __shared__ float Bs[16][64];

    int bm = blockIdx.y * 128;
    int bn = blockIdx.x * 64;
    int tid = threadIdx.x;
    int tx = tid & 15;
    int ty = tid >> 4;

    float acc[8][4];
    #pragma unroll
    for (int i = 0; i < 8; i++)
        #pragma unroll
        for (int j = 0; j < 4; j++) acc[i][j] = 0.0f;

    for (int k0 = 0; k0 < K; k0 += 16) {
        #pragma unroll
        for (int i = 0; i < 8; i++) {
            int e = tid + i * 256;
            int m = e >> 4, kk = e & 15;
            int gk = k0 + kk;
            As[kk][m] = (gk < K) ? A[(size_t)(bm + m) * lda + gk] : 0.0f;
        }
        {
            int kk = tid >> 4;
            int nc = (tid & 15) << 2;
            int gk = k0 + kk;
            float4 v = make_float4(0.f, 0.f, 0.f, 0.f);
            if (gk < K) v = *(const float4*)(W + (size_t)gk * N + bn + nc);
            *(float4*)&Bs[kk][nc] = v;
        }
        __syncthreads();
        #pragma unroll
        for (int kk = 0; kk < 16; kk++) {
            float4 a0 = *(const float4*)&As[kk][ty * 8];
            float4 a1 = *(const float4*)&As[kk][ty * 8 + 4];
            float4 bv = *(const float4*)&Bs[kk][tx * 4];
            float av[8] = {a0.x, a0.y, a0.z, a0.w, a1.x, a1.y, a1.z, a1.w};
            float bw[4] = {bv.x, bv.y, bv.z, bv.w};
            #pragma unroll
            for (int i = 0; i < 8; i++)
                #pragma unroll
                for (int j = 0; j < 4; j++)
                    acc[i][j] = fmaf(av[i], bw[j], acc[i][j]);
        }
        __syncthreads();
    }

    float4 bb = *(const float4*)(bias + bn + tx * 4);
    #pragma unroll
    for (int i = 0; i < 8; i++) {
        float4 o;
        o.x = acc[i][0] + bb.x;
        o.y = acc[i][1] + bb.y;
        o.z = acc[i][2] + bb.z;
        o.w = acc[i][3] + bb.w;
        *(float4*)(C + (size_t)(bm + ty * 8 + i) * N + bn + tx * 4) = o;
    }
}

// ---------------- fused attention v3 ----------------
// v1 shape (QT=16, 512 threads, 256 CTAs) + conflict-free dim-major K tiles +
// cp.async double buffering + match_any-aggregated histogram atomics.
// Per-accumulator FMA order identical to v1 -> bit-identical output.
#define QT  16
#define CKC 128
#define NCH (NK / CKC)   // 16
#define CAP 128

struct AttnSmem3 {
    float  s[QT][NK];              // 131072 B
    float4 Ks4[2][16][CKC + 1];    // 66048 B (dim-major, +1 pad)
    float4 qs4[QT][16];            // 4096 B
    int    hist[QT][256];          // 16384 B
    float  plist[QT][CAP];         // 8192 B
    unsigned short list[QT][CAP];  // 4096 B
    int    cnt[QT];                // 64 B
};                                  // 229952 B  (< 232448 limit)

__device__ __forceinline__ unsigned key_of(float f) {
    unsigned u = __float_as_uint(f);
    return (u & 0x80000000u) ? ~u : (u | 0x80000000u);
}
__device__ __forceinline__ float inv_key(unsigned k) {
    unsigned u = (k & 0x80000000u) ? (k ^ 0x80000000u) : ~k;
    return __uint_as_float(u);
}

__device__ __forceinline__ void cp_async16(void* smem_dst, const void* gmem_src) {
    uint32_t sa = (uint32_t)__cvta_generic_to_shared(smem_dst);
    asm volatile("cp.async.cg.shared.global [%0], [%1], 16;" :: "r"(sa), "l"(gmem_src));
}
__device__ __forceinline__ void cp_commit() {
    asm volatile("cp.async.commit_group;");
}
template <int N>
__device__ __forceinline__ void cp_wait() {
    asm volatile("cp.async.wait_group %0;" :: "n"(N) : "memory");
}

// chunk rows -> Ks4[buf][d4][row]; gmem side coalesced (16 lanes span one K row)
__device__ __forceinline__ void load_chunk(AttnSmem3* sm, const float* __restrict__ Kg,
                                           int base_k, int kc, int buf, int tid, int hoff) {
    const float* src = Kg + (size_t)(base_k + kc) * INNER + hoff;
    #pragma unroll
    for (int i = 0; i < 4; i++) {
        int e = tid + i * 512;
        int row = e >> 4, d4 = e & 15;
        cp_async16(&sm->Ks4[buf][d4][row], src + (size_t)row * INNER + d4 * 4);
    }
}

__global__ __launch_bounds__(512) void attn_kernel(
    const float* __restrict__ Qg, const float* __restrict__ Kg,
    const float* __restrict__ Vg,
    float* __restrict__ Og)
{
    extern __shared__ char smraw[];
    AttnSmem3* sm = reinterpret_cast<AttnSmem3*>(smraw);

    int tile = blockIdx.x;           // b*1024 + h*128 + qt
    int qt = tile & 127;
    int h  = (tile >> 7) & 7;
    int b  = tile >> 10;
    int tid = threadIdx.x;

    int base_q = b * NQ + qt * QT;
    int base_k = b * NK;
    int hoff = h * DH;

    // stage q (16 rows x 16 float4)
    if (tid < QT * 16) {
        int r = tid >> 4, d4 = tid & 15;
        sm->qs4[r][d4] = *(const float4*)(Qg + (size_t)(base_q + r) * INNER + hoff + d4 * 4);
    }

    // preload chunk 0
    load_chunk(sm, Kg, base_k, 0, 0, tid, hoff);
    cp_commit();

    int qi2 = tid >> 6;        // 0..7 -> rows {2qi2, 2qi2+1}
    int kl  = tid & 63;        // k cols {kl, kl+64} in chunk
    int q0r = 2 * qi2, q1r = q0r + 1;

    for (int c = 0; c < NCH; c++) {
        if (c + 1 < NCH) {
            load_chunk(sm, Kg, base_k, (c + 1) * CKC, (c + 1) & 1, tid, hoff);
            cp_commit();
            cp_wait<1>();
        } else {
            cp_wait<0>();
        }
        __syncthreads();

        int buf = c & 1;
        float a00 = 0.f, a01 = 0.f, a10 = 0.f, a11 = 0.f;
        #pragma unroll
        for (int d4 = 0; d4 < 16; d4++) {
            float4 qa = sm->qs4[q0r][d4];             // warp-uniform -> broadcast
            float4 qb = sm->qs4[q1r][d4];
            float4 ka = sm->Ks4[buf][d4][kl];         // lanes adjacent -> conflict-free
            float4 kb = sm->Ks4[buf][d4][kl + 64];
            a00 = fmaf(qa.x, ka.x, a00); a00 = fmaf(qa.y, ka.y, a00);
            a00 = fmaf(qa.z, ka.z, a00); a00 = fmaf(qa.w, ka.w, a00);
            a01 = fmaf(qa.x, kb.x, a01); a01 = fmaf(qa.y, kb.y, a01);
            a01 = fmaf(qa.z, kb.z, a01); a01 = fmaf(qa.w, kb.w, a01);
            a10 = fmaf(qb.x, ka.x, a10); a10 = fmaf(qb.y, ka.y, a10);
            a10 = fmaf(qb.z, ka.z, a10); a10 = fmaf(qb.w, ka.w, a10);
            a11 = fmaf(qb.x, kb.x, a11); a11 = fmaf(qb.y, kb.y, a11);
            a11 = fmaf(qb.z, kb.z, a11); a11 = fmaf(qb.w, kb.w, a11);
        }
        int kc = c * CKC;
        sm->s[q0r][kc + kl]      = a00 * 0.125f;
        sm->s[q0r][kc + kl + 64] = a01 * 0.125f;
        sm->s[q1r][kc + kl]      = a10 * 0.125f;
        sm->s[q1r][kc + kl + 64] = a11 * 0.125f;
        __syncthreads();
    }

    // ---- per-warp exact radix select of the 64th-largest value ----
    const unsigned full = 0xFFFFFFFFu;
    int warp = tid >> 5, lane = tid & 31;
    int r = warp;                       // 16 warps == QT rows

    unsigned prefix = 0, pmask = 0;
    int krem = TOPKK;
    #pragma unroll
    for (int shift = 24; shift >= 0; shift -= 8) {
        for (int bi = lane; bi < 256; bi += 32) sm->hist[r][bi] = 0;
        __syncwarp();
        for (int j = lane; j < NK; j += 32) {
            unsigned u = key_of(sm->s[r][j]);
            bool pred = ((u & pmask) == prefix);
            unsigned active = __ballot_sync(full, pred);
            if (pred) {
                int bin = (u >> shift) & 255;
                unsigned mm = __match_any_sync(active, bin);
                int leader = __ffs(mm) - 1;
                if (lane == leader) atomicAdd(&sm->hist[r][bin], __popc(mm));
            }
        }
        __syncwarp();
        int basebin = 255 - 8 * lane;
        int gsum = 0;
        #pragma unroll
        for (int i = 0; i < 8; i++) gsum += sm->hist[r][basebin - i];
        int inc = gsum;
        #pragma unroll
        for (int off = 1; off < 32; off <<= 1) {
            int v = __shfl_up_sync(full, inc, off);
            if (lane >= off) inc += v;
        }
        int excl = inc - gsum;
        unsigned bal = __ballot_sync(full, (excl < krem) && (krem <= inc));
        int selLane = __ffs(bal) - 1;
        int exclSel = __shfl_sync(full, excl, selLane);
        int need = krem - exclSel;
        int gb = 255 - 8 * selLane;
        int selBin = -1, cc = 0, newNeed = 0;
        for (int i = 0; i < 8; i++) {
            int hh = sm->hist[r][gb - i];
            if (selBin < 0 && need <= cc + hh) { selBin = gb - i; newNeed = need - cc; }
            cc += hh;
        }
        krem = newNeed;
        prefix |= ((unsigned)selBin) << shift;
        pmask  |= (0xFFu << shift);
        __syncwarp();
    }
    float vkf = inv_key(prefix);

    // ---- deterministic gather of kept indices + row max ----
    int cbase = 0;
    float m = -FLT_MAX;
    for (int j0 = 0; j0 < NK; j0 += 32) {
        int j = j0 + lane;
        float sv = sm->s[r][j];
        bool keep = (sv >= vkf);
        unsigned bal = __ballot_sync(full, keep);
        if (keep) {
            int pos = cbase + __popc(bal & ((1u << lane) - 1u));
            if (pos < CAP) sm->list[r][pos] = (unsigned short)j;
            m = fmaxf(m, sv);
        }
        cbase += __popc(bal);
    }
    #pragma unroll
    for (int off = 16; off; off >>= 1) m = fmaxf(m, __shfl_xor_sync(full, m, off));
    if (lane == 0) sm->cnt[r] = cbase;
    __syncwarp();
    int n = sm->cnt[r];

    float acc0 = 0.f, acc1 = 0.f, sum = 0.f;
    const float* Vb = Vg + (size_t)base_k * INNER + hoff;

    if (n <= CAP) {
        float ls = 0.f;
        for (int e = lane; e < n; e += 32) {
            int j = sm->list[r][e];
            float p = expf(sm->s[r][j] - m);
            sm->plist[r][e] = p;
            ls += p;
        }
        #pragma unroll
        for (int off = 16; off; off >>= 1) ls += __shfl_xor_sync(full, ls, off);
        sum = ls;
        __syncwarp();
        #pragma unroll 4
        for (int e = 0; e < n; e++) {
            float p = sm->plist[r][e];
            int j = sm->list[r][e];
            const float* vp = Vb + (size_t)j * INNER;
            acc0 = fmaf(p, vp[lane],      acc0);
            acc1 = fmaf(p, vp[lane + 32], acc1);
        }
    } else {
        float ls = 0.f;
        for (int j = 0; j < NK; j++) {
            float sv = sm->s[r][j];
            if (sv >= vkf) {
                float p = expf(sv - m);
                ls += p;
                const float* vp = Vb + (size_t)j * INNER;
                acc0 = fmaf(p, vp[lane],      acc0);
                acc1 = fmaf(p, vp[lane + 32], acc1);
            }
        }
        sum = ls;
    }

    float invs = 1.0f / sum;
    float* op = Og + (size_t)(base_q + r) * INNER + hoff;
    op[lane]      = acc0 * invs;
    op[lane + 32] = acc1 * invs;
}

// ---------------- launch ----------------
extern "C" void kernel_launch(void* const* d_in, const int* in_sizes, int n_in,
                              void* d_out, int out_size)
{
    const float* x       = (const float*)d_in[0];
    const float* context = (const float*)d_in[1];
    // d_in[2]/d_in[3] are the bool masks; constant all-True in this problem.
    const float* Wq = (const float*)d_in[4];
    const float* bq = (const float*)d_in[5];
    const float* Wk = (const float*)d_in[6];
    const float* bk = (const float*)d_in[7];
    const float* Wv = (const float*)d_in[8];
    const float* bv = (const float*)d_in[9];
    const float* Wo = (const float*)d_in[10];
    const float* bo = (const float*)d_in[11];
    float* out = (float*)d_out;

    void *pAq, *pAk, *pQ, *pK, *pV, *pO;
    cudaGetSymbolAddress(&pAq, g_Aq);
    cudaGetSymbolAddress(&pAk, g_Ak);
    cudaGetSymbolAddress(&pQ,  g_Q);
    cudaGetSymbolAddress(&pK,  g_K);
    cudaGetSymbolAddress(&pV,  g_V);
    cudaGetSymbolAddress(&pO,  g_O);
    float* Aq = (float*)pAq; float* Ak = (float*)pAk;
    float* Qd = (float*)pQ;  float* Kd = (float*)pK;
    float* Vd = (float*)pV;  float* Od = (float*)pO;

    cudaFuncSetAttribute(attn_kernel, cudaFuncAttributeMaxDynamicSharedMemorySize,
                         (int)sizeof(AttnSmem3));

    enc_kernel<<<(NQ + 255) / 256, 256>>>();

    int tot = MROWS * DWP;
    concat_kernel<<<(tot + 255) / 256, 256>>>(x, context);

    dim3 gg(INNER / 64, MROWS / 128);   // (8, 32)
    gemm_bias<<<gg, 256>>>(Aq, DWP, Wq, bq, Qd, MROWS, INNER, DWP);
    gemm_bias<<<gg, 256>>>(Ak, DWP, Wk, bk, Kd, MROWS, INNER, DWP);
    gemm_bias<<<gg, 256>>>(context, DIMM, Wv, bv, Vd, MROWS, INNER, DIMM);

    attn_kernel<<<BB * HH * (NQ / QT), 512, sizeof(AttnSmem3)>>>(Qd, Kd, Vd, Od);

    gemm_bias<<<gg, 256>>>(Od, INNER, Wo, bo, out, MROWS, DIMM, INNER);
}

// round 6
// speedup vs baseline: 1.6759x; 1.5452x over previous
#include <cuda_runtime.h>
#include <math.h>
#include <cfloat>
#include <stdint.h>

// ---------------- problem constants ----------------
#define BB     2
#define NQ     2048
#define NK     2048
#define DIMM   512
#define HH     8
#define DH     64
#define INNER  512
#define NBANDS 32
#define DWP    577      // DIM + 2*NUM_BANDS + 1
#define TOPKK  64
#define MROWS  (BB*NQ)  // 4096

// ---------------- scratch (device globals; no cudaMalloc allowed) ----------------
__device__ float g_enc[NQ * 65];
__device__ float g_Aq[(size_t)MROWS * DWP];
__device__ float g_Ak[(size_t)MROWS * DWP];
__device__ float g_Q [(size_t)MROWS * INNER];
__device__ float g_K [(size_t)MROWS * INNER];
__device__ float g_V [(size_t)MROWS * INNER];
__device__ float g_O [(size_t)MROWS * INNER];

// ---------------- fourier encode ----------------
__global__ void enc_kernel() {
    int i = blockIdx.x * blockDim.x + threadIdx.x;
    if (i >= NQ) return;
    float step = 2.0f / 2047.0f;
    float pos = fmaf((float)i, step, -1.0f);
    g_enc[i * 65 + 64] = pos;
    #pragma unroll 4
    for (int b = 0; b < NBANDS; b++) {
        float sc = 1.0f + 29.0f * (float)b / 31.0f;   // linspace(1, 30, 32)
        float xs = (pos * sc) * 3.14159265358979323846f;
        g_enc[i * 65 + b]          = sinf(xs);
        g_enc[i * 65 + NBANDS + b] = cosf(xs);
    }
}

// ---------------- concat [x | enc] and [context | enc] ----------------
__global__ void concat_kernel(const float* __restrict__ x, const float* __restrict__ ctx) {
    int idx = blockIdx.x * blockDim.x + threadIdx.x;
    const int total = MROWS * DWP;
    if (idx >= total) return;
    int row = idx / DWP;
    int c   = idx - row * DWP;
    if (c < DIMM) {
        g_Aq[idx] = x  [(size_t)row * DIMM + c];
        g_Ak[idx] = ctx[(size_t)row * DIMM + c];
    } else {
        int i = row & (NQ - 1);
        float e = g_enc[i * 65 + (c - DIMM)];
        g_Aq[idx] = e;
        g_Ak[idx] = e;
    }
}

// ---------------- fp32 tiled GEMM (unchanged: bit-exact projections) ----------------
__global__ __launch_bounds__(256) void gemm_bias(
    const float* __restrict__ A, int lda,
    const float* __restrict__ W,
    const float* __restrict__ bias,
    float* __restrict__ C,
    int M, int N, int K)
{
    __shared__ float As[16][132];
    __shared__ float Bs[16][64];

    int bm = blockIdx.y * 128;
    int bn = blockIdx.x * 64;
    int tid = threadIdx.x;
    int tx = tid & 15;
    int ty = tid >> 4;

    float acc[8][4];
    #pragma unroll
    for (int i = 0; i < 8; i++)
        #pragma unroll
        for (int j = 0; j < 4; j++) acc[i][j] = 0.0f;

    for (int k0 = 0; k0 < K; k0 += 16) {
        #pragma unroll
        for (int i = 0; i < 8; i++) {
            int e = tid + i * 256;
            int m = e >> 4, kk = e & 15;
            int gk = k0 + kk;
            As[kk][m] = (gk < K) ? A[(size_t)(bm + m) * lda + gk] : 0.0f;
        }
        {
            int kk = tid >> 4;
            int nc = (tid & 15) << 2;
            int gk = k0 + kk;
            float4 v = make_float4(0.f, 0.f, 0.f, 0.f);
            if (gk < K) v = *(const float4*)(W + (size_t)gk * N + bn + nc);
            *(float4*)&Bs[kk][nc] = v;
        }
        __syncthreads();
        #pragma unroll
        for (int kk = 0; kk < 16; kk++) {
            float4 a0 = *(const float4*)&As[kk][ty * 8];
            float4 a1 = *(const float4*)&As[kk][ty * 8 + 4];
            float4 bv = *(const float4*)&Bs[kk][tx * 4];
            float av[8] = {a0.x, a0.y, a0.z, a0.w, a1.x, a1.y, a1.z, a1.w};
            float bw[4] = {bv.x, bv.y, bv.z, bv.w};
            #pragma unroll
            for (int i = 0; i < 8; i++)
                #pragma unroll
                for (int j = 0; j < 4; j++)
                    acc[i][j] = fmaf(av[i], bw[j], acc[i][j]);
        }
        __syncthreads();
    }

    float4 bb = *(const float4*)(bias + bn + tx * 4);
    #pragma unroll
    for (int i = 0; i < 8; i++) {
        float4 o;
        o.x = acc[i][0] + bb.x;
        o.y = acc[i][1] + bb.y;
        o.z = acc[i][2] + bb.z;
        o.w = acc[i][3] + bb.w;
        *(float4*)(C + (size_t)(bm + ty * 8 + i) * N + bn + tx * 4) = o;
    }
}

// ---------------- fused attention v4 ----------------
// v1 control flow (plain synchronous loads, single buffer, 512 threads, 2048 CTAs)
// with (a) dim-major conflict-free K tiles Ks4[d4][row], (b) 4q x 2k register tile
// (CKC=256) to halve smem reads per FMA. Per-accumulator FMA order identical to
// v1 -> bit-identical scores/selection/output.
#define QT  16
#define CKC 256
#define NCH (NK / CKC)   // 8
#define CAP 128

struct AttnSmem4 {
    float  s[QT][NK];              // 131072 B
    float4 Ks4[16][CKC + 1];       // 65792 B (dim-major, +1 pad)
    float4 qs4[QT][16];            // 4096 B
    int    hist[QT][256];          // 16384 B
    float  plist[QT][CAP];         // 8192 B
    unsigned short list[QT][CAP];  // 4096 B
    int    cnt[QT];                // 64 B
};                                  // 229696 B (< 232448 limit)

__device__ __forceinline__ unsigned key_of(float f) {
    unsigned u = __float_as_uint(f);
    return (u & 0x80000000u) ? ~u : (u | 0x80000000u);
}
__device__ __forceinline__ float inv_key(unsigned k) {
    unsigned u = (k & 0x80000000u) ? (k ^ 0x80000000u) : ~k;
    return __uint_as_float(u);
}

__global__ __launch_bounds__(512) void attn_kernel(
    const float* __restrict__ Qg, const float* __restrict__ Kg,
    const float* __restrict__ Vg,
    float* __restrict__ Og)
{
    extern __shared__ char smraw[];
    AttnSmem4* sm = reinterpret_cast<AttnSmem4*>(smraw);

    int tile = blockIdx.x;           // b*1024 + h*128 + qt
    int qt = tile & 127;
    int h  = (tile >> 7) & 7;
    int b  = tile >> 10;
    int tid = threadIdx.x;

    int base_q = b * NQ + qt * QT;
    int base_k = b * NK;
    int hoff = h * DH;

    // stage q (16 rows x 16 float4)
    if (tid < QT * 16) {
        int r = tid >> 4, d4 = tid & 15;
        sm->qs4[r][d4] = *(const float4*)(Qg + (size_t)(base_q + r) * INNER + hoff + d4 * 4);
    }
    __syncthreads();

    int g  = tid >> 7;        // 0..3 -> q rows {4g .. 4g+3} (warp-uniform)
    int kl = tid & 127;       // k cols {kl, kl+128} in chunk
    int r0 = 4 * g;

    for (int c = 0; c < NCH; c++) {
        // cooperative K-chunk load: gmem coalesced (16 lanes span one K row),
        // stored dim-major for conflict-free compute reads
        {
            const float* src = Kg + (size_t)(base_k + c * CKC) * INNER + hoff;
            #pragma unroll
            for (int i = 0; i < 8; i++) {
                int e = tid + i * 512;
                int row = e >> 4, d4 = e & 15;
                sm->Ks4[d4][row] = *(const float4*)(src + (size_t)row * INNER + d4 * 4);
            }
        }
        __syncthreads();

        float a0[2] = {0.f, 0.f};
        float a1[2] = {0.f, 0.f};
        float a2[2] = {0.f, 0.f};
        float a3[2] = {0.f, 0.f};
        #pragma unroll
        for (int d4 = 0; d4 < 16; d4++) {
            float4 q0 = sm->qs4[r0 + 0][d4];          // warp-uniform -> broadcast
            float4 q1 = sm->qs4[r0 + 1][d4];
            float4 q2 = sm->qs4[r0 + 2][d4];
            float4 q3 = sm->qs4[r0 + 3][d4];
            float4 ka = sm->Ks4[d4][kl];              // lanes adjacent -> conflict-free
            float4 kb = sm->Ks4[d4][kl + 128];
            a0[0] = fmaf(q0.x, ka.x, a0[0]); a0[0] = fmaf(q0.y, ka.y, a0[0]);
            a0[0] = fmaf(q0.z, ka.z, a0[0]); a0[0] = fmaf(q0.w, ka.w, a0[0]);
            a0[1] = fmaf(q0.x, kb.x, a0[1]); a0[1] = fmaf(q0.y, kb.y, a0[1]);
            a0[1] = fmaf(q0.z, kb.z, a0[1]); a0[1] = fmaf(q0.w, kb.w, a0[1]);
            a1[0] = fmaf(q1.x, ka.x, a1[0]); a1[0] = fmaf(q1.y, ka.y, a1[0]);
            a1[0] = fmaf(q1.z, ka.z, a1[0]); a1[0] = fmaf(q1.w, ka.w, a1[0]);
            a1[1] = fmaf(q1.x, kb.x, a1[1]); a1[1] = fmaf(q1.y, kb.y, a1[1]);
            a1[1] = fmaf(q1.z, kb.z, a1[1]); a1[1] = fmaf(q1.w, kb.w, a1[1]);
            a2[0] = fmaf(q2.x, ka.x, a2[0]); a2[0] = fmaf(q2.y, ka.y, a2[0]);
            a2[0] = fmaf(q2.z, ka.z, a2[0]); a2[0] = fmaf(q2.w, ka.w, a2[0]);
            a2[1] = fmaf(q2.x, kb.x, a2[1]); a2[1] = fmaf(q2.y, kb.y, a2[1]);
            a2[1] = fmaf(q2.z, kb.z, a2[1]); a2[1] = fmaf(q2.w, kb.w, a2[1]);
            a3[0] = fmaf(q3.x, ka.x, a3[0]); a3[0] = fmaf(q3.y, ka.y, a3[0]);
            a3[0] = fmaf(q3.z, ka.z, a3[0]); a3[0] = fmaf(q3.w, ka.w, a3[0]);
            a3[1] = fmaf(q3.x, kb.x, a3[1]); a3[1] = fmaf(q3.y, kb.y, a3[1]);
            a3[1] = fmaf(q3.z, kb.z, a3[1]); a3[1] = fmaf(q3.w, kb.w, a3[1]);
        }
        int kc = c * CKC;
        sm->s[r0 + 0][kc + kl]       = a0[0] * 0.125f;
        sm->s[r0 + 0][kc + kl + 128] = a0[1] * 0.125f;
        sm->s[r0 + 1][kc + kl]       = a1[0] * 0.125f;
        sm->s[r0 + 1][kc + kl + 128] = a1[1] * 0.125f;
        sm->s[r0 + 2][kc + kl]       = a2[0] * 0.125f;
        sm->s[r0 + 2][kc + kl + 128] = a2[1] * 0.125f;
        sm->s[r0 + 3][kc + kl]       = a3[0] * 0.125f;
        sm->s[r0 + 3][kc + kl + 128] = a3[1] * 0.125f;
        __syncthreads();
    }

    // ---- per-warp exact radix select of the 64th-largest value ----
    const unsigned full = 0xFFFFFFFFu;
    int warp = tid >> 5, lane = tid & 31;
    int r = warp;                       // 16 warps == QT rows

    unsigned prefix = 0, pmask = 0;
    int krem = TOPKK;
    #pragma unroll
    for (int shift = 24; shift >= 0; shift -= 8) {
        for (int bi = lane; bi < 256; bi += 32) sm->hist[r][bi] = 0;
        __syncwarp();
        for (int j = lane; j < NK; j += 32) {
            unsigned u = key_of(sm->s[r][j]);
            if ((u & pmask) == prefix)
                atomicAdd(&sm->hist[r][(u >> shift) & 255], 1);
        }
        __syncwarp();
        int basebin = 255 - 8 * lane;
        int gsum = 0;
        #pragma unroll
        for (int i = 0; i < 8; i++) gsum += sm->hist[r][basebin - i];
        int inc = gsum;
        #pragma unroll
        for (int off = 1; off < 32; off <<= 1) {
            int v = __shfl_up_sync(full, inc, off);
            if (lane >= off) inc += v;
        }
        int excl = inc - gsum;
        unsigned bal = __ballot_sync(full, (excl < krem) && (krem <= inc));
        int selLane = __ffs(bal) - 1;
        int exclSel = __shfl_sync(full, excl, selLane);
        int need = krem - exclSel;
        int gb = 255 - 8 * selLane;
        int selBin = -1, cc = 0, newNeed = 0;
        for (int i = 0; i < 8; i++) {
            int hh = sm->hist[r][gb - i];
            if (selBin < 0 && need <= cc + hh) { selBin = gb - i; newNeed = need - cc; }
            cc += hh;
        }
        krem = newNeed;
        prefix |= ((unsigned)selBin) << shift;
        pmask  |= (0xFFu << shift);
        __syncwarp();
    }
    float vkf = inv_key(prefix);

    // ---- deterministic gather of kept indices + row max ----
    int cbase = 0;
    float m = -FLT_MAX;
    for (int j0 = 0; j0 < NK; j0 += 32) {
        int j = j0 + lane;
        float sv = sm->s[r][j];
        bool keep = (sv >= vkf);
        unsigned bal = __ballot_sync(full, keep);
        if (keep) {
            int pos = cbase + __popc(bal & ((1u << lane) - 1u));
            if (pos < CAP) sm->list[r][pos] = (unsigned short)j;
            m = fmaxf(m, sv);
        }
        cbase += __popc(bal);
    }
    #pragma unroll
    for (int off = 16; off; off >>= 1) m = fmaxf(m, __shfl_xor_sync(full, m, off));
    if (lane == 0) sm->cnt[r] = cbase;
    __syncwarp();
    int n = sm->cnt[r];

    float acc0 = 0.f, acc1 = 0.f, sum = 0.f;
    const float* Vb = Vg + (size_t)base_k * INNER + hoff;

    if (n <= CAP) {
        float ls = 0.f;
        for (int e = lane; e < n; e += 32) {
            int j = sm->list[r][e];
            float p = expf(sm->s[r][j] - m);
            sm->plist[r][e] = p;
            ls += p;
        }
        #pragma unroll
        for (int off = 16; off; off >>= 1) ls += __shfl_xor_sync(full, ls, off);
        sum = ls;
        __syncwarp();
        #pragma unroll 4
        for (int e = 0; e < n; e++) {
            float p = sm->plist[r][e];
            int j = sm->list[r][e];
            const float* vp = Vb + (size_t)j * INNER;
            acc0 = fmaf(p, vp[lane],      acc0);
            acc1 = fmaf(p, vp[lane + 32], acc1);
        }
    } else {
        float ls = 0.f;
        for (int j = 0; j < NK; j++) {
            float sv = sm->s[r][j];
            if (sv >= vkf) {
                float p = expf(sv - m);
                ls += p;
                const float* vp = Vb + (size_t)j * INNER;
                acc0 = fmaf(p, vp[lane],      acc0);
                acc1 = fmaf(p, vp[lane + 32], acc1);
            }
        }
        sum = ls;
    }

    float invs = 1.0f / sum;
    float* op = Og + (size_t)(base_q + r) * INNER + hoff;
    op[lane]      = acc0 * invs;
    op[lane + 32] = acc1 * invs;
}

// ---------------- launch ----------------
extern "C" void kernel_launch(void* const* d_in, const int* in_sizes, int n_in,
                              void* d_out, int out_size)
{
    const float* x       = (const float*)d_in[0];
    const float* context = (const float*)d_in[1];
    // d_in[2]/d_in[3] are the bool masks; constant all-True in this problem.
    const float* Wq = (const float*)d_in[4];
    const float* bq = (const float*)d_in[5];
    const float* Wk = (const float*)d_in[6];
    const float* bk = (const float*)d_in[7];
    const float* Wv = (const float*)d_in[8];
    const float* bv = (const float*)d_in[9];
    const float* Wo = (const float*)d_in[10];
    const float* bo = (const float*)d_in[11];
    float* out = (float*)d_out;

    void *pAq, *pAk, *pQ, *pK, *pV, *pO;
    cudaGetSymbolAddress(&pAq, g_Aq);
    cudaGetSymbolAddress(&pAk, g_Ak);
    cudaGetSymbolAddress(&pQ,  g_Q);
    cudaGetSymbolAddress(&pK,  g_K);
    cudaGetSymbolAddress(&pV,  g_V);
    cudaGetSymbolAddress(&pO,  g_O);
    float* Aq = (float*)pAq; float* Ak = (float*)pAk;
    float* Qd = (float*)pQ;  float* Kd = (float*)pK;
    float* Vd = (float*)pV;  float* Od = (float*)pO;

    cudaFuncSetAttribute(attn_kernel, cudaFuncAttributeMaxDynamicSharedMemorySize,
                         (int)sizeof(AttnSmem4));

    enc_kernel<<<(NQ + 255) / 256, 256>>>();

    int tot = MROWS * DWP;
    concat_kernel<<<(tot + 255) / 256, 256>>>(x, context);

    dim3 gg(INNER / 64, MROWS / 128);   // (8, 32)
    gemm_bias<<<gg, 256>>>(Aq, DWP, Wq, bq, Qd, MROWS, INNER, DWP);
    gemm_bias<<<gg, 256>>>(Ak, DWP, Wk, bk, Kd, MROWS, INNER, DWP);
    gemm_bias<<<gg, 256>>>(context, DIMM, Wv, bv, Vd, MROWS, INNER, DIMM);

    attn_kernel<<<BB * HH * (NQ / QT), 512, sizeof(AttnSmem4)>>>(Qd, Kd, Vd, Od);

    gemm_bias<<<gg, 256>>>(Od, INNER, Wo, bo, out, MROWS, DIMM, INNER);
}